// round 1
// baseline (speedup 1.0000x reference)
#include <cuda_runtime.h>
#include <cuda_fp16.h>
#include <cstdint>

#define NN    512
#define SS    64
#define TRS   20
#define STEPS 20
#define NB    (TRS*STEPS)      /* 400 */
#define NBLK  128
#define NODES_PER_BLK (NN/NBLK) /* 4 */

// ---------------- device globals (no runtime allocation allowed) ------------
__device__ float  g_lap[NN*NN];            // w scratch, then full laplacian (fp32, incl diag)
__device__ __half g_lap_h[NN*NN];          // w_n (off-diag part) fp16 for tensor-core GEMM
__device__ float  g_rowsumraw[NN];
__device__ float  g_sqpart[NN];
__device__ float  g_rowsum[NN];            // normalized row sums (diag magnitude)
__device__ float  g_invnorm;
__device__ float  g_G0[NB*NN*SS];          // w_n @ e0 for all 400 (tr,step) batches: 52.4 MB
__device__ float  g_EmBuf[2*NN];           // ping-pong global Em exchange
__device__ volatile unsigned g_count;      // grid barrier counter (reset each launch)

// ---------------- prep: w, norm, laplacian ----------------------------------
__global__ void prep_w(const float* __restrict__ sc, const float* __restrict__ gc) {
    int i = blockIdx.x, tid = threadIdx.x;
    float rs = 0.f, ssq = 0.f;
    for (int j = tid; j < NN; j += 256) {
        float wv = 0.5f * (expf(gc[i*NN + j]) * sc[i*NN + j]
                         + expf(gc[j*NN + i]) * sc[j*NN + i]);
        g_lap[i*NN + j] = wv;
        rs += wv; ssq += wv*wv;
    }
    __shared__ float sr[8], sq[8];
    #pragma unroll
    for (int o = 16; o; o >>= 1) {
        rs  += __shfl_down_sync(0xffffffffu, rs, o);
        ssq += __shfl_down_sync(0xffffffffu, ssq, o);
    }
    if ((tid & 31) == 0) { sr[tid>>5] = rs; sq[tid>>5] = ssq; }
    __syncthreads();
    if (tid == 0) {
        float r = 0.f, s2 = 0.f;
        #pragma unroll
        for (int w = 0; w < 8; w++) { r += sr[w]; s2 += sq[w]; }
        g_rowsumraw[i] = r; g_sqpart[i] = s2;
    }
}

__global__ void prep_norm() {
    int tid = threadIdx.x;               // 512 threads
    __shared__ float sm[512];
    sm[tid] = g_sqpart[tid];
    __syncthreads();
    for (int o = 256; o; o >>= 1) { if (tid < o) sm[tid] += sm[tid+o]; __syncthreads(); }
    if (tid == 0) {
        g_invnorm = 1.0f / sqrtf(sm[0]);
        g_count = 0u;                    // reset grid barrier for this launch
    }
}

__global__ void prep_lap() {
    int i = blockIdx.x, tid = threadIdx.x;
    float inv  = g_invnorm;
    float diag = g_rowsumraw[i] * inv;
    for (int j = tid; j < NN; j += 256) {
        float wn = g_lap[i*NN + j] * inv;       // w_n (diag entries are 0)
        g_lap_h[i*NN + j] = __float2half_rn(wn);
        g_lap[i*NN + j]   = (j == i) ? (wn - diag) : wn;  // full laplacian fp32
    }
    if (tid == 0) g_rowsum[i] = diag;
}

// ---------------- batched GEMM: G0[b] = w_n @ e0[b]  (fp16 MMA, fp32 accum) --
__global__ void __launch_bounds__(512) gemm_k(const float* __restrict__ nE0) {
    __shared__ __half BsT[64][18];               // [n(sample)][k], padded
    const int b = blockIdx.x;
    const int tid = threadIdx.x, warp = tid >> 5, lane = tid & 31;
    const float* B = nE0 + (size_t)b * (NN*SS);  // e0[k][s], k-major

    float acc[2][8][4];
    #pragma unroll
    for (int rt = 0; rt < 2; rt++)
        #pragma unroll
        for (int j = 0; j < 8; j++)
            #pragma unroll
            for (int c = 0; c < 4; c++) acc[rt][j][c] = 0.f;

    const int arow = lane >> 2, acol = (lane & 3) * 2;
    const int bn   = lane >> 2, bk   = (lane & 3) * 2;

    for (int k0 = 0; k0 < NN; k0 += 16) {
        __syncthreads();
        {
            int e = tid, kk = e >> 6, sI = e & 63;
            BsT[sI][kk] = __float2half_rn(B[(k0 + kk)*SS + sI]);
            e = tid + 512; kk = e >> 6; sI = e & 63;
            BsT[sI][kk] = __float2half_rn(B[(k0 + kk)*SS + sI]);
        }
        __syncthreads();

        unsigned bf0[8], bf1[8];
        #pragma unroll
        for (int j = 0; j < 8; j++) {
            bf0[j] = *(const unsigned*)&BsT[j*8 + bn][bk];
            bf1[j] = *(const unsigned*)&BsT[j*8 + bn][bk + 8];
        }
        #pragma unroll
        for (int rt = 0; rt < 2; rt++) {
            const __half* Ap = g_lap_h + (size_t)(warp*32 + rt*16 + arow)*NN + k0 + acol;
            unsigned a0 = *(const unsigned*)Ap;
            unsigned a1 = *(const unsigned*)(Ap + 8*NN);
            unsigned a2 = *(const unsigned*)(Ap + 8);
            unsigned a3 = *(const unsigned*)(Ap + 8*NN + 8);
            #pragma unroll
            for (int j = 0; j < 8; j++) {
                asm volatile(
                    "mma.sync.aligned.m16n8k16.row.col.f32.f16.f16.f32 "
                    "{%0,%1,%2,%3},{%4,%5,%6,%7},{%8,%9},{%0,%1,%2,%3};\n"
                    : "+f"(acc[rt][j][0]), "+f"(acc[rt][j][1]),
                      "+f"(acc[rt][j][2]), "+f"(acc[rt][j][3])
                    : "r"(a0), "r"(a1), "r"(a2), "r"(a3), "r"(bf0[j]), "r"(bf1[j]));
            }
        }
    }
    float* C = g_G0 + (size_t)b * (NN*SS);
    #pragma unroll
    for (int rt = 0; rt < 2; rt++) {
        int r = warp*32 + rt*16 + (lane >> 2);
        #pragma unroll
        for (int j = 0; j < 8; j++) {
            int c = j*8 + (lane & 3)*2;
            *(float2*)&C[r*SS + c]       = make_float2(acc[rt][j][0], acc[rt][j][1]);
            *(float2*)&C[(r+8)*SS + c]   = make_float2(acc[rt][j][2], acc[rt][j][3]);
        }
    }
}

// ---------------- main sequential loop (persistent, grid-synced) ------------
__device__ __forceinline__ float tanh_pos(float x) {  // tanh(relu(x))
    x = fmaxf(x, 0.0f);
    float e = __expf(-2.0f * x);
    return __fdividef(1.0f - e, 1.0f + e);
}
__device__ __forceinline__ float h_tf(float a, float bb, float d, float z) {
    float x   = fmaf(a, z, -bb);
    float num = 1e-5f + fabsf(x);
    float den = fmaf(1e-5f, d, fabsf(1.0f - __expf(-d * x)));
    return __fdividef(num, den);
}

__global__ void __launch_bounds__(256) main_k(
    const float* __restrict__ ext,  const float* __restrict__ hx,
    const float* __restrict__ nE0,  const float* __restrict__ nI0,
    const float* __restrict__ nE,   const float* __restrict__ nI,
    const float* __restrict__ nbold,
    const float* __restrict__ pg,   const float* __restrict__ pgEE,
    const float* __restrict__ pgIE, const float* __restrict__ pgEI,
    const float* __restrict__ pstdin, const float* __restrict__ pstdout,
    float* __restrict__ out)
{
    const int tid = threadIdx.x;
    const int nl = tid >> 6, sIdx = tid & 63;
    const int n  = blockIdx.x * NODES_PER_BLK + nl;
    const int warp = tid >> 5, lane = tid & 31;

    __shared__ float s_hxE[4], s_hxI[4], s_mv[8], s_re[8], s_ri[8];

    const float g     = pg[0];
    const float gEE   = 0.001f + fmaxf(pgEE[0], 0.0f);
    const float gIE   = 0.001f + fmaxf(pgIE[0], 0.0f);
    const float gEI   = 0.001f + fmaxf(pgEI[0], 0.0f);
    const float sin_e = 0.02f + fmaxf(pstdin[0], 0.0f);
    const float sout  = fmaxf(pstdout[0], 0.0f);
    const float sq_si = 0.22360680f * sin_e;   // sqrt(DT)*std_in_e
    const float rowsum_n = g_rowsum[n];

    float x = 0.f, f = 0.f, v = 0.f, q = 0.f;
    if (sIdx == 0) {
        float hE0 = hx[n*6 + 0];
        s_hxE[nl] = hE0; s_hxI[nl] = hx[n*6 + 1];
        x = hx[n*6 + 2]; f = hx[n*6 + 3]; v = hx[n*6 + 4]; q = hx[n*6 + 5];
        g_EmBuf[n] = hE0;                      // buffer 0 = initial hxE
    }
    unsigned target = NBLK;
    __syncthreads();
    if (tid == 0) {
        __threadfence();
        atomicAdd((unsigned*)&g_count, 1u);
        while (g_count < target) { }
        __threadfence();
    }
    __syncthreads();

    for (int b = 0; b < NB; b++) {
        const int tr = b / STEPS, st = b - tr * STEPS;
        const float hxEv = s_hxE[nl], hxIv = s_hxI[nl];

        const size_t base = (size_t)b*(NN*SS) + (size_t)n*SS + sIdx;
        const float e0  = nE0[base];
        const float i0  = nI0[base];
        const float eEv = nE[base];
        const float eIv = nI[base];
        const float G0v = g_G0[base];
        const float exv = ext[(n*STEPS + st)*TRS + tr];

        // matvec: lv[n] = lap[n,:] @ Em_prev   (lap includes the -rowsum diag)
        const float* lr = g_lap + n*NN;
        const float* em = g_EmBuf + (b & 1)*NN;
        float acc = 0.f;
        #pragma unroll
        for (int u = 0; u < 8; u++) acc = fmaf(lr[sIdx + 64*u], em[sIdx + 64*u], acc);
        #pragma unroll
        for (int o = 16; o; o >>= 1) acc += __shfl_down_sync(0xffffffffu, acc, o);
        if (lane == 0) s_mv[warp] = acc;
        __syncthreads();
        const float lv = s_mv[2*nl] + s_mv[2*nl + 1];

        // per-sample dynamics
        float E = fmaf(0.02f, e0, hxEv);
        float I = fmaf(0.001f, i0, hxIv);
        float lapE = lv + 0.02f * (G0v - rowsum_n * e0);   // exact diag term in fp32
        float IE = tanh_pos(0.32f + 0.02f*exv + gEE*E + g*lapE - gIE*I);
        float II = tanh_pos(0.224f + gEI*E - I);
        float rE = h_tf(310.0f, 125.0f, 0.16f,  IE);
        float rI = h_tf(615.0f, 177.0f, 0.087f, II);
        float En = E + 0.05f * (0.641f*(1.0f - E)*rE - 10.0f*E) + sq_si*eEv;
        float In = I + 0.05f * (rI - 100.0f*I) + sq_si*eIv;
        float Ep = tanh_pos(En);
        float Ip = tanh_pos(In);

        #pragma unroll
        for (int o = 16; o; o >>= 1) {
            Ep += __shfl_down_sync(0xffffffffu, Ep, o);
            Ip += __shfl_down_sync(0xffffffffu, Ip, o);
        }
        if (lane == 0) { s_re[warp] = Ep; s_ri[warp] = Ip; }
        __syncthreads();

        if (sIdx == 0) {
            float Em = fmaxf((s_re[2*nl] + s_re[2*nl+1]) * (1.0f/64.0f), 1e-5f);
            float Im = fmaxf((s_ri[2*nl] + s_ri[2*nl+1]) * (1.0f/64.0f), 1e-5f);
            float v_a = powf(v, 3.125f);
            float xn = x + 0.05f * (Em - x/0.65f - (f - 1.0f)/0.41f);
            float fn = f + 0.05f * x;
            float vn = v + 0.05f * (f - v_a) / 0.98f;
            float qn = q + 0.05f * (f*(1.0f - powf(0.66f, 1.0f/f))/0.34f - q*v_a/v) / 0.98f;
            x = tanhf(xn);
            f = 1.0f + tanhf(fn - 1.0f);
            v = 1.0f + tanhf(vn - 1.0f);
            q = 1.0f + tanhf(qn - 1.0f);
            s_hxE[nl] = Em; s_hxI[nl] = Im;
            g_EmBuf[((b + 1) & 1)*NN + n] = Em;
            if (st == STEPS - 1) {
                out[n*TRS + tr] = sout * nbold[tr*NN + n]
                    + (100.0f*0.02f/0.34f) * (2.38f*(1.0f - q)
                                            + 2.0f*(1.0f - q/v)
                                            + 0.48f*(1.0f - v));
            }
        }

        // grid barrier (monotonic counter; reset each launch in prep_norm)
        target += NBLK;
        __syncthreads();
        if (tid == 0) {
            __threadfence();
            atomicAdd((unsigned*)&g_count, 1u);
            while (g_count < target) { }
            __threadfence();
        }
        __syncthreads();
    }
}

// ---------------- launch ----------------------------------------------------
extern "C" void kernel_launch(void* const* d_in, const int* in_sizes, int n_in,
                              void* d_out, int out_size) {
    (void)in_sizes; (void)n_in; (void)out_size;
    const float* external = (const float*)d_in[0];
    const float* hx       = (const float*)d_in[1];
    /* d_in[2] = hE : unused by the reference */
    const float* sc       = (const float*)d_in[3];
    const float* gc       = (const float*)d_in[4];
    const float* pg       = (const float*)d_in[5];
    const float* pgEE     = (const float*)d_in[6];
    const float* pgIE     = (const float*)d_in[7];
    const float* pgEI     = (const float*)d_in[8];
    const float* pstdin   = (const float*)d_in[9];
    const float* pstdout  = (const float*)d_in[10];
    const float* nE0      = (const float*)d_in[11];
    const float* nI0      = (const float*)d_in[12];
    const float* nEn      = (const float*)d_in[13];
    const float* nIn      = (const float*)d_in[14];
    const float* nbold    = (const float*)d_in[15];
    float* out = (float*)d_out;

    prep_w  <<<NN, 256>>>(sc, gc);
    prep_norm<<<1, 512>>>();
    prep_lap<<<NN, 256>>>();
    gemm_k  <<<NB, 512>>>(nE0);
    main_k  <<<NBLK, 256>>>(external, hx, nE0, nI0, nEn, nIn, nbold,
                            pg, pgEE, pgIE, pgEI, pstdin, pstdout, out);
}